// round 14
// baseline (speedup 1.0000x reference)
#include <cuda_runtime.h>
#include <cstdint>

// Problem constants (fixed by the dataset)
#define NN 50000
#define EE 800000
#define HH 64
#define GG 128
#define CC 16
#define CAP 64   // per-node bucket capacity (mean deg = 16; P(deg>63) ~ e^-39)

// ---------------- device scratch (static, no allocations) ----------------
__device__ int   g_deg[NN];                    // in-degree / bucket fill
__device__ float g_dinv[NN];
__device__ int   g_srcs[(size_t)NN * CAP];     // bucketed CSR
__device__ float g_feat[(size_t)NN * HH];      // (X@W)*dinv working buffer
__device__ float g_h1[(size_t)NN * HH];        // layer-1 output (post relu)
__device__ int   g_goff[GG + 1];
__device__ int   g_is64;

// ---------------- index dtype handling ----------------
__device__ __forceinline__ int idx_at(const void* p, int is64, long long i) {
    if (is64) return (int)__ldg(((const long long*)p) + i);
    return __ldg(((const int*)p) + i);
}

__device__ __forceinline__ unsigned f2tf(float f) {
    unsigned u;
    asm("cvt.rna.tf32.f32 %0, %1;" : "=r"(u) : "f"(f));
    return u;
}

// Zero counters + detect index dtype (int64 vs int32).
__global__ void zero_kernel(const void* __restrict__ ei) {
    int i = blockIdx.x * blockDim.x + threadIdx.x;
    int stride = gridDim.x * blockDim.x;
    for (; i < NN; i += stride) g_deg[i] = 0;
    if (blockIdx.x == 0 && threadIdx.x == 0) {
        const unsigned long long* p = (const unsigned long long*)ei;
        int ok = 1;
        for (int t = 0; t < 16; t++)
            if (p[t] >= (unsigned long long)NN) ok = 0;
        g_is64 = ok;
    }
}

// Single-pass bucketed CSR build, unrolled x4 for atomic-latency overlap.
__global__ __launch_bounds__(256) void scatter_kernel(const void* __restrict__ ei) {
    const int U = 4;
    int is64 = g_is64;
    int stride = gridDim.x * blockDim.x;
    int base = blockIdx.x * blockDim.x + threadIdx.x;

    int s[U], d[U], p[U];
    bool ok[U];
#pragma unroll
    for (int u = 0; u < U; u++) {
        int e = base + u * stride;
        ok[u] = (e < EE);
        if (ok[u]) {
            s[u] = idx_at(ei, is64, e);
            d[u] = idx_at(ei, is64, (long long)EE + e);
        }
    }
#pragma unroll
    for (int u = 0; u < U; u++)
        if (ok[u]) p[u] = atomicAdd(&g_deg[d[u]], 1);
#pragma unroll
    for (int u = 0; u < U; u++)
        if (ok[u] && p[u] < CAP) g_srcs[(size_t)d[u] * CAP + p[u]] = s[u];
}

// dinv from final degrees + graph offsets from sorted-batch boundaries.
__global__ void meta_kernel(const void* __restrict__ bat) {
    int is64 = g_is64;
    int i = blockIdx.x * blockDim.x + threadIdx.x;
    int stride = gridDim.x * blockDim.x;
    for (int n = i; n < NN; n += stride) {
        g_dinv[n] = rsqrtf((float)(g_deg[n] + 1));
        int b = idx_at(bat, is64, n);
        int bp = (n == 0) ? -1 : idx_at(bat, is64, n - 1);
        for (int g = bp + 1; g <= b; g++) g_goff[g] = n;
        if (n == NN - 1)
            for (int g = b + 1; g <= GG; g++) g_goff[g] = NN;
    }
}

// Tensor-core GEMM: out[row,:] = (X[row,:] @ W) * dinv[row].
// m16n8k8 tf32 mma. 64-row blocks, 128 threads = 4 warps x 16 rows.
// PTX tf32 fragment layout:
//   A: a0=(g,t) a1=(g+8,t) a2=(g,t+4) a3=(g+8,t+4)
//   B: b0=(k=t,n=g) b1=(k=t+4,n=g)
//   C: c0=(g,2t) c1=(g,2t+1) c2=(g+8,2t) c3=(g+8,2t+1)
__global__ __launch_bounds__(128) void gemm_tc(const float* __restrict__ X,
                                               const float* __restrict__ W,
                                               float* __restrict__ out,
                                               int n) {
    __shared__ unsigned Xs[64][68];     // X tile, pre-converted to tf32
    __shared__ unsigned Wt[64][68];     // W converted to tf32, [k][n]
    const int tid = threadIdx.x;
    const int brow = blockIdx.x * 64;

    for (int t = tid; t < 64 * 16; t += 128) {
        int r = t >> 4, c = (t & 15) << 2;
        float4 w = *(const float4*)(W + r * 64 + c);
        Wt[r][c] = f2tf(w.x); Wt[r][c + 1] = f2tf(w.y);
        Wt[r][c + 2] = f2tf(w.z); Wt[r][c + 3] = f2tf(w.w);
        int grow = brow + r;
        float4 v = make_float4(0.f, 0.f, 0.f, 0.f);
        if (grow < n) v = *(const float4*)(X + (size_t)grow * 64 + c);
        Xs[r][c] = f2tf(v.x); Xs[r][c + 1] = f2tf(v.y);
        Xs[r][c + 2] = f2tf(v.z); Xs[r][c + 3] = f2tf(v.w);
    }
    __syncthreads();

    const int wid = tid >> 5, lane = tid & 31;
    const int g = lane >> 2, t4 = lane & 3;
    const int wr = wid * 16;

    float acc[8][4];
#pragma unroll
    for (int nt = 0; nt < 8; nt++)
#pragma unroll
        for (int j = 0; j < 4; j++) acc[nt][j] = 0.f;

#pragma unroll
    for (int kt = 0; kt < 8; kt++) {
        int k0 = kt * 8;
        unsigned a0 = Xs[wr + g][k0 + t4];
        unsigned a1 = Xs[wr + g + 8][k0 + t4];
        unsigned a2 = Xs[wr + g][k0 + t4 + 4];
        unsigned a3 = Xs[wr + g + 8][k0 + t4 + 4];
#pragma unroll
        for (int nt = 0; nt < 8; nt++) {
            unsigned b0 = Wt[k0 + t4][nt * 8 + g];
            unsigned b1 = Wt[k0 + t4 + 4][nt * 8 + g];
            asm("mma.sync.aligned.m16n8k8.row.col.f32.tf32.tf32.f32 "
                "{%0,%1,%2,%3}, {%4,%5,%6,%7}, {%8,%9}, {%0,%1,%2,%3};"
                : "+f"(acc[nt][0]), "+f"(acc[nt][1]),
                  "+f"(acc[nt][2]), "+f"(acc[nt][3])
                : "r"(a0), "r"(a1), "r"(a2), "r"(a3), "r"(b0), "r"(b1));
        }
    }

    int row0 = brow + wr + g;
    int row1 = row0 + 8;
    if (row0 < n) {
        float dv = g_dinv[row0];
#pragma unroll
        for (int nt = 0; nt < 8; nt++)
            *(float2*)(out + (size_t)row0 * 64 + nt * 8 + 2 * t4) =
                make_float2(acc[nt][0] * dv, acc[nt][1] * dv);
    }
    if (row1 < n) {
        float dv = g_dinv[row1];
#pragma unroll
        for (int nt = 0; nt < 8; nt++)
            *(float2*)(out + (size_t)row1 * 64 + nt * 8 + 2 * t4) =
                make_float2(acc[nt][2] * dv, acc[nt][3] * dv);
    }
}

// Pull-style aggregation: one warp per node, 2 edges per step (half-warps),
// inner loop unrolled x4 -> 8 independent gathers in flight per warp.
template <bool RELU>
__global__ __launch_bounds__(256) void agg_kernel(const float* __restrict__ gb,
                                                  const float* __restrict__ bias,
                                                  float* __restrict__ out) {
    int warp = (blockIdx.x * blockDim.x + threadIdx.x) >> 5;
    if (warp >= NN) return;
    int lane = threadIdx.x & 31;
    int sub = lane >> 4;          // which of 2 edges per step
    int fc = (lane & 15) << 2;    // feature offset (float4)
    int beg = warp * CAP;
    int end = beg + min(g_deg[warp], CAP);

    float4 accA, accB, accC, accD;
    accB = make_float4(0.f, 0.f, 0.f, 0.f);
    accC = accB; accD = accB;
    if (sub == 0) {               // self-loop term loaded once by half-warp 0
        accA = *(const float4*)(gb + (size_t)warp * 64 + fc);
    } else {
        accA = make_float4(0.f, 0.f, 0.f, 0.f);
    }

    int e = beg + sub;
    for (; e + 6 < end; e += 8) {
        int s0 = __ldg(&g_srcs[e]);
        int s1 = __ldg(&g_srcs[e + 2]);
        int s2 = __ldg(&g_srcs[e + 4]);
        int s3 = __ldg(&g_srcs[e + 6]);
        float4 v0 = __ldg((const float4*)(gb + (size_t)s0 * 64 + fc));
        float4 v1 = __ldg((const float4*)(gb + (size_t)s1 * 64 + fc));
        float4 v2 = __ldg((const float4*)(gb + (size_t)s2 * 64 + fc));
        float4 v3 = __ldg((const float4*)(gb + (size_t)s3 * 64 + fc));
        accA.x += v0.x; accA.y += v0.y; accA.z += v0.z; accA.w += v0.w;
        accB.x += v1.x; accB.y += v1.y; accB.z += v1.z; accB.w += v1.w;
        accC.x += v2.x; accC.y += v2.y; accC.z += v2.z; accC.w += v2.w;
        accD.x += v3.x; accD.y += v3.y; accD.z += v3.z; accD.w += v3.w;
    }
    for (; e < end; e += 2) {
        int s0 = __ldg(&g_srcs[e]);
        float4 v0 = __ldg((const float4*)(gb + (size_t)s0 * 64 + fc));
        accA.x += v0.x; accA.y += v0.y; accA.z += v0.z; accA.w += v0.w;
    }
    accA.x += accB.x + accC.x + accD.x;
    accA.y += accB.y + accC.y + accD.y;
    accA.z += accB.z + accC.z + accD.z;
    accA.w += accB.w + accC.w + accD.w;

    // combine the two half-warps
    accA.x += __shfl_xor_sync(0xffffffffu, accA.x, 16);
    accA.y += __shfl_xor_sync(0xffffffffu, accA.y, 16);
    accA.z += __shfl_xor_sync(0xffffffffu, accA.z, 16);
    accA.w += __shfl_xor_sync(0xffffffffu, accA.w, 16);

    if (sub == 0) {
        float dv = g_dinv[warp];
        float4 b = __ldg((const float4*)(bias + fc));
        float4 o;
        o.x = fmaf(accA.x, dv, b.x);
        o.y = fmaf(accA.y, dv, b.y);
        o.z = fmaf(accA.z, dv, b.z);
        o.w = fmaf(accA.w, dv, b.w);
        if (RELU) {
            o.x = fmaxf(o.x, 0.f); o.y = fmaxf(o.y, 0.f);
            o.z = fmaxf(o.z, 0.f); o.w = fmaxf(o.w, 0.f);
        }
        *(float4*)(out + (size_t)warp * 64 + fc) = o;
    }
}

// Fused mean pool + classifier: one block per graph, 64 threads.
__global__ __launch_bounds__(64) void poolcls_kernel(
        const float* __restrict__ h, float* __restrict__ reps,
        const float* __restrict__ Wc1, const float* __restrict__ bc1,
        const float* __restrict__ Wc2, const float* __restrict__ bc2,
        float* __restrict__ logits) {
    __shared__ float rep[64];
    __shared__ float tbuf[64];
    int g = blockIdx.x, tid = threadIdx.x;
    int beg = g_goff[g], end = g_goff[g + 1];
    float s = 0.f;
    for (int i = beg; i < end; i++) s += __ldg(h + (size_t)i * 64 + tid);
    float c = (float)max(end - beg, 1);
    float r = s / c;
    reps[g * 64 + tid] = r;
    rep[tid] = r;
    __syncthreads();
    float acc = bc1[tid];
#pragma unroll
    for (int k = 0; k < 64; k++) acc = fmaf(rep[k], __ldg(Wc1 + k * 64 + tid), acc);
    tbuf[tid] = fmaxf(acc, 0.f);
    __syncthreads();
    if (tid < CC) {
        float a = bc2[tid];
#pragma unroll
        for (int k = 0; k < 64; k++) a = fmaf(tbuf[k], __ldg(Wc2 + k * CC + tid), a);
        logits[g * CC + tid] = a;
    }
}

extern "C" void kernel_launch(void* const* d_in, const int* in_sizes, int n_in,
                              void* d_out, int out_size) {
    const float* x   = (const float*)d_in[0];
    const void*  ei  = d_in[1];
    const void*  bat = d_in[2];
    const float* W1  = (const float*)d_in[3];
    const float* b1  = (const float*)d_in[4];
    const float* W2  = (const float*)d_in[5];
    const float* b2  = (const float*)d_in[6];
    const float* Wc1 = (const float*)d_in[7];
    const float* bc1 = (const float*)d_in[8];
    const float* Wc2 = (const float*)d_in[9];
    const float* bc2 = (const float*)d_in[10];

    float* out_h   = (float*)d_out;                       // [NN, 64]
    float* out_rep = out_h + (size_t)NN * HH;             // [128, 64]
    float* out_log = out_rep + (size_t)GG * HH;           // [128, 16]

    void* pv;
    cudaGetSymbolAddress(&pv, g_feat);
    float* p_feat = (float*)pv;
    cudaGetSymbolAddress(&pv, g_h1);
    float* p_h1 = (float*)pv;

    const int gemm_blocks = (NN + 63) / 64;               // 782
    const int agg_blocks = (NN * 32 + 255) / 256;
    const int scat_blocks = (EE + 256 * 4 - 1) / (256 * 4);

    zero_kernel<<<128, 256>>>(ei);
    scatter_kernel<<<scat_blocks, 256>>>(ei);
    meta_kernel<<<256, 256>>>(bat);

    // Layer 1
    gemm_tc<<<gemm_blocks, 128>>>(x, W1, p_feat, NN);
    agg_kernel<true><<<agg_blocks, 256>>>(p_feat, b1, p_h1);

    // Layer 2 (output h, no relu)
    gemm_tc<<<gemm_blocks, 128>>>(p_h1, W2, p_feat, NN);
    agg_kernel<false><<<agg_blocks, 256>>>(p_feat, b2, out_h);

    // Fused pool + classifier
    poolcls_kernel<<<GG, 64>>>(out_h, out_rep, Wc1, bc1, Wc2, bc2, out_log);
}

// round 15
// speedup vs baseline: 1.1174x; 1.1174x over previous
#include <cuda_runtime.h>
#include <cstdint>

// Problem constants (fixed by the dataset)
#define NN 50000
#define EE 800000
#define HH 64
#define GG 128
#define CC 16
#define CAP 64   // per-node bucket capacity (mean deg = 16; P(deg>63) ~ e^-39)

// ---------------- device scratch (static, no allocations) ----------------
__device__ int   g_deg[NN];                    // in-degree / bucket fill
__device__ int   g_srcs[(size_t)NN * CAP];     // bucketed CSR
__device__ float g_feat[(size_t)NN * HH];      // (X@W)*dinv working buffer
__device__ float g_h1[(size_t)NN * HH];        // layer-1 output (post relu)
__device__ int   g_goff[GG + 1];
__device__ int   g_is64;

// ---------------- index dtype handling ----------------
__device__ __forceinline__ int idx_at(const void* p, int is64, long long i) {
    if (is64) return (int)__ldg(((const long long*)p) + i);
    return __ldg(((const int*)p) + i);
}

__device__ __forceinline__ unsigned f2tf(float f) {
    unsigned u;
    asm("cvt.rna.tf32.f32 %0, %1;" : "=r"(u) : "f"(f));
    return u;
}

// Zero deg + detect index dtype + graph offsets from sorted batch.
__global__ void zero_kernel(const void* __restrict__ ei, const void* __restrict__ bat) {
    __shared__ int s_is64;
    if (threadIdx.x == 0) {
        const unsigned long long* p = (const unsigned long long*)ei;
        int ok = 1;
        for (int t = 0; t < 16; t++)
            if (p[t] >= (unsigned long long)NN) ok = 0;
        s_is64 = ok;
        if (blockIdx.x == 0) g_is64 = ok;
    }
    __syncthreads();
    int is64 = s_is64;
    int i = blockIdx.x * blockDim.x + threadIdx.x;
    int stride = gridDim.x * blockDim.x;
    for (int n = i; n < NN; n += stride) {
        g_deg[n] = 0;
        // graph boundary detection on sorted batch
        int b = idx_at(bat, is64, n);
        int bp = (n == 0) ? -1 : idx_at(bat, is64, n - 1);
        for (int g = bp + 1; g <= b; g++) g_goff[g] = n;
        if (n == NN - 1)
            for (int g = b + 1; g <= GG; g++) g_goff[g] = NN;
    }
}

// Single-pass bucketed CSR build, unrolled x8 for atomic-latency overlap.
__global__ __launch_bounds__(256) void scatter_kernel(const void* __restrict__ ei) {
    const int U = 8;
    int is64 = g_is64;
    int stride = gridDim.x * blockDim.x;
    int base = blockIdx.x * blockDim.x + threadIdx.x;

    int s[U], d[U], p[U];
    bool ok[U];
#pragma unroll
    for (int u = 0; u < U; u++) {
        int e = base + u * stride;
        ok[u] = (e < EE);
        if (ok[u]) {
            s[u] = idx_at(ei, is64, e);
            d[u] = idx_at(ei, is64, (long long)EE + e);
        }
    }
#pragma unroll
    for (int u = 0; u < U; u++)
        if (ok[u]) p[u] = atomicAdd(&g_deg[d[u]], 1);
#pragma unroll
    for (int u = 0; u < U; u++)
        if (ok[u] && p[u] < CAP) g_srcs[(size_t)d[u] * CAP + p[u]] = s[u];
}

// Tensor-core GEMM: out[row,:] = (X[row,:] @ W) * rsqrt(deg[row]+1).
// m16n8k8 tf32 mma. 64-row blocks, 128 threads = 4 warps x 16 rows.
// PTX tf32 fragment layout:
//   A: a0=(g,t) a1=(g+8,t) a2=(g,t+4) a3=(g+8,t+4)
//   B: b0=(k=t,n=g) b1=(k=t+4,n=g)
//   C: c0=(g,2t) c1=(g,2t+1) c2=(g+8,2t) c3=(g+8,2t+1)
__global__ __launch_bounds__(128) void gemm_tc(const float* __restrict__ X,
                                               const float* __restrict__ W,
                                               float* __restrict__ out,
                                               int n) {
    __shared__ unsigned Xs[64][68];     // X tile, pre-converted to tf32
    __shared__ unsigned Wt[64][68];     // W converted to tf32, [k][n]
    const int tid = threadIdx.x;
    const int brow = blockIdx.x * 64;

    for (int t = tid; t < 64 * 16; t += 128) {
        int r = t >> 4, c = (t & 15) << 2;
        float4 w = *(const float4*)(W + r * 64 + c);
        Wt[r][c] = f2tf(w.x); Wt[r][c + 1] = f2tf(w.y);
        Wt[r][c + 2] = f2tf(w.z); Wt[r][c + 3] = f2tf(w.w);
        int grow = brow + r;
        float4 v = make_float4(0.f, 0.f, 0.f, 0.f);
        if (grow < n) v = *(const float4*)(X + (size_t)grow * 64 + c);
        Xs[r][c] = f2tf(v.x); Xs[r][c + 1] = f2tf(v.y);
        Xs[r][c + 2] = f2tf(v.z); Xs[r][c + 3] = f2tf(v.w);
    }
    __syncthreads();

    const int wid = tid >> 5, lane = tid & 31;
    const int g = lane >> 2, t4 = lane & 3;
    const int wr = wid * 16;

    float acc[8][4];
#pragma unroll
    for (int nt = 0; nt < 8; nt++)
#pragma unroll
        for (int j = 0; j < 4; j++) acc[nt][j] = 0.f;

#pragma unroll
    for (int kt = 0; kt < 8; kt++) {
        int k0 = kt * 8;
        unsigned a0 = Xs[wr + g][k0 + t4];
        unsigned a1 = Xs[wr + g + 8][k0 + t4];
        unsigned a2 = Xs[wr + g][k0 + t4 + 4];
        unsigned a3 = Xs[wr + g + 8][k0 + t4 + 4];
#pragma unroll
        for (int nt = 0; nt < 8; nt++) {
            unsigned b0 = Wt[k0 + t4][nt * 8 + g];
            unsigned b1 = Wt[k0 + t4 + 4][nt * 8 + g];
            asm("mma.sync.aligned.m16n8k8.row.col.f32.tf32.tf32.f32 "
                "{%0,%1,%2,%3}, {%4,%5,%6,%7}, {%8,%9}, {%0,%1,%2,%3};"
                : "+f"(acc[nt][0]), "+f"(acc[nt][1]),
                  "+f"(acc[nt][2]), "+f"(acc[nt][3])
                : "r"(a0), "r"(a1), "r"(a2), "r"(a3), "r"(b0), "r"(b1));
        }
    }

    int row0 = brow + wr + g;
    int row1 = row0 + 8;
    if (row0 < n) {
        float dv = rsqrtf((float)(__ldg(&g_deg[row0]) + 1));
#pragma unroll
        for (int nt = 0; nt < 8; nt++)
            *(float2*)(out + (size_t)row0 * 64 + nt * 8 + 2 * t4) =
                make_float2(acc[nt][0] * dv, acc[nt][1] * dv);
    }
    if (row1 < n) {
        float dv = rsqrtf((float)(__ldg(&g_deg[row1]) + 1));
#pragma unroll
        for (int nt = 0; nt < 8; nt++)
            *(float2*)(out + (size_t)row1 * 64 + nt * 8 + 2 * t4) =
                make_float2(acc[nt][2] * dv, acc[nt][3] * dv);
    }
}

// Pull-style aggregation: one warp per node, 2 edges per step (half-warps),
// inner loop unrolled x2 -> 4 independent gathers in flight per warp. (R12)
template <bool RELU>
__global__ __launch_bounds__(256) void agg_kernel(const float* __restrict__ gb,
                                                  const float* __restrict__ bias,
                                                  float* __restrict__ out) {
    int warp = (blockIdx.x * blockDim.x + threadIdx.x) >> 5;
    if (warp >= NN) return;
    int lane = threadIdx.x & 31;
    int sub = lane >> 4;          // which of 2 edges per step
    int fc = (lane & 15) << 2;    // feature offset (float4)
    int deg = g_deg[warp];
    int beg = warp * CAP;
    int end = beg + min(deg, CAP);

    float4 accA, accB = make_float4(0.f, 0.f, 0.f, 0.f);
    if (sub == 0) {               // self-loop term loaded once by half-warp 0
        accA = *(const float4*)(gb + (size_t)warp * 64 + fc);
    } else {
        accA = make_float4(0.f, 0.f, 0.f, 0.f);
    }

    int e = beg + sub;
    for (; e + 2 < end; e += 4) {
        int s0 = __ldg(&g_srcs[e]);
        int s1 = __ldg(&g_srcs[e + 2]);
        float4 v0 = __ldg((const float4*)(gb + (size_t)s0 * 64 + fc));
        float4 v1 = __ldg((const float4*)(gb + (size_t)s1 * 64 + fc));
        accA.x += v0.x; accA.y += v0.y; accA.z += v0.z; accA.w += v0.w;
        accB.x += v1.x; accB.y += v1.y; accB.z += v1.z; accB.w += v1.w;
    }
    if (e < end) {
        int s0 = __ldg(&g_srcs[e]);
        float4 v0 = __ldg((const float4*)(gb + (size_t)s0 * 64 + fc));
        accA.x += v0.x; accA.y += v0.y; accA.z += v0.z; accA.w += v0.w;
    }
    accA.x += accB.x; accA.y += accB.y; accA.z += accB.z; accA.w += accB.w;

    // combine the two half-warps
    accA.x += __shfl_xor_sync(0xffffffffu, accA.x, 16);
    accA.y += __shfl_xor_sync(0xffffffffu, accA.y, 16);
    accA.z += __shfl_xor_sync(0xffffffffu, accA.z, 16);
    accA.w += __shfl_xor_sync(0xffffffffu, accA.w, 16);

    if (sub == 0) {
        float dv = rsqrtf((float)(deg + 1));
        float4 b = __ldg((const float4*)(bias + fc));
        float4 o;
        o.x = fmaf(accA.x, dv, b.x);
        o.y = fmaf(accA.y, dv, b.y);
        o.z = fmaf(accA.z, dv, b.z);
        o.w = fmaf(accA.w, dv, b.w);
        if (RELU) {
            o.x = fmaxf(o.x, 0.f); o.y = fmaxf(o.y, 0.f);
            o.z = fmaxf(o.z, 0.f); o.w = fmaxf(o.w, 0.f);
        }
        *(float4*)(out + (size_t)warp * 64 + fc) = o;
    }
}

// Fused mean pool + classifier: one block per graph, 64 threads.
__global__ __launch_bounds__(64) void poolcls_kernel(
        const float* __restrict__ h, float* __restrict__ reps,
        const float* __restrict__ Wc1, const float* __restrict__ bc1,
        const float* __restrict__ Wc2, const float* __restrict__ bc2,
        float* __restrict__ logits) {
    __shared__ float rep[64];
    __shared__ float tbuf[64];
    int g = blockIdx.x, tid = threadIdx.x;
    int beg = g_goff[g], end = g_goff[g + 1];
    float s = 0.f;
    for (int i = beg; i < end; i++) s += __ldg(h + (size_t)i * 64 + tid);
    float c = (float)max(end - beg, 1);
    float r = s / c;
    reps[g * 64 + tid] = r;
    rep[tid] = r;
    __syncthreads();
    float acc = bc1[tid];
#pragma unroll
    for (int k = 0; k < 64; k++) acc = fmaf(rep[k], __ldg(Wc1 + k * 64 + tid), acc);
    tbuf[tid] = fmaxf(acc, 0.f);
    __syncthreads();
    if (tid < CC) {
        float a = bc2[tid];
#pragma unroll
        for (int k = 0; k < 64; k++) a = fmaf(tbuf[k], __ldg(Wc2 + k * CC + tid), a);
        logits[g * CC + tid] = a;
    }
}

extern "C" void kernel_launch(void* const* d_in, const int* in_sizes, int n_in,
                              void* d_out, int out_size) {
    const float* x   = (const float*)d_in[0];
    const void*  ei  = d_in[1];
    const void*  bat = d_in[2];
    const float* W1  = (const float*)d_in[3];
    const float* b1  = (const float*)d_in[4];
    const float* W2  = (const float*)d_in[5];
    const float* b2  = (const float*)d_in[6];
    const float* Wc1 = (const float*)d_in[7];
    const float* bc1 = (const float*)d_in[8];
    const float* Wc2 = (const float*)d_in[9];
    const float* bc2 = (const float*)d_in[10];

    float* out_h   = (float*)d_out;                       // [NN, 64]
    float* out_rep = out_h + (size_t)NN * HH;             // [128, 64]
    float* out_log = out_rep + (size_t)GG * HH;           // [128, 16]

    void* pv;
    cudaGetSymbolAddress(&pv, g_feat);
    float* p_feat = (float*)pv;
    cudaGetSymbolAddress(&pv, g_h1);
    float* p_h1 = (float*)pv;

    const int gemm_blocks = (NN + 63) / 64;               // 782
    const int agg_blocks = (NN * 32 + 255) / 256;
    const int scat_blocks = (EE + 256 * 8 - 1) / (256 * 8);   // 391

    zero_kernel<<<128, 256>>>(ei, bat);
    scatter_kernel<<<scat_blocks, 256>>>(ei);

    // Layer 1
    gemm_tc<<<gemm_blocks, 128>>>(x, W1, p_feat, NN);
    agg_kernel<true><<<agg_blocks, 256>>>(p_feat, b1, p_h1);

    // Layer 2 (output h, no relu)
    gemm_tc<<<gemm_blocks, 128>>>(p_h1, W2, p_feat, NN);
    agg_kernel<false><<<agg_blocks, 256>>>(p_feat, b2, out_h);

    // Fused pool + classifier
    poolcls_kernel<<<GG, 64>>>(out_h, out_rep, Wc1, bc1, Wc2, bc2, out_log);
}

// round 16
// speedup vs baseline: 1.1449x; 1.0246x over previous
#include <cuda_runtime.h>
#include <cstdint>

// Problem constants (fixed by the dataset)
#define NN 50000
#define EE 800000
#define HH 64
#define GG 128
#define CC 16
#define CAP 64   // per-node bucket capacity (mean deg = 16; P(deg>63) ~ e^-39)
#define GRROWS 96   // gemm rows per block (6 warps x 16)

// ---------------- device scratch (static, no allocations) ----------------
__device__ int   g_deg[NN];                    // in-degree / bucket fill (left 0 after each run)
__device__ float g_dinv[NN];
__device__ int   g_srcs[(size_t)NN * CAP];     // bucketed CSR
__device__ float g_feat[(size_t)NN * HH];      // (X@W)*dinv working buffer
__device__ float g_h1[(size_t)NN * HH];        // layer-1 output (post relu)
__device__ int   g_goff[GG + 1];
__device__ int   g_is64;

// ---------------- index dtype handling ----------------
__device__ __forceinline__ int idx_at(const void* p, int is64, long long i) {
    if (is64) return (int)__ldg(((const long long*)p) + i);
    return __ldg(((const int*)p) + i);
}

__device__ __forceinline__ int detect64(const void* ei) {
    const unsigned long long* p = (const unsigned long long*)ei;
    int ok = 1;
    for (int t = 0; t < 16; t++)
        if (p[t] >= (unsigned long long)NN) ok = 0;
    return ok;
}

__device__ __forceinline__ unsigned f2tf(float f) {
    unsigned u;
    asm("cvt.rna.tf32.f32 %0, %1;" : "=r"(u) : "f"(f));
    return u;
}

// Single-pass bucketed CSR build, unrolled x4 for atomic-latency overlap.
// g_deg starts at 0 (statics on first run; poolcls resets it at the end of
// every run). Detects index dtype per-block; block 0 publishes for meta.
__global__ __launch_bounds__(256) void scatter_kernel(const void* __restrict__ ei) {
    __shared__ int s_is64;
    if (threadIdx.x == 0) {
        int ok = detect64(ei);
        s_is64 = ok;
        if (blockIdx.x == 0) g_is64 = ok;
    }
    __syncthreads();
    const int U = 4;
    int is64 = s_is64;
    int stride = gridDim.x * blockDim.x;
    int base = blockIdx.x * blockDim.x + threadIdx.x;

    int s[U], d[U], p[U];
    bool ok[U];
#pragma unroll
    for (int u = 0; u < U; u++) {
        int e = base + u * stride;
        ok[u] = (e < EE);
        if (ok[u]) {
            s[u] = idx_at(ei, is64, e);
            d[u] = idx_at(ei, is64, (long long)EE + e);
        }
    }
#pragma unroll
    for (int u = 0; u < U; u++)
        if (ok[u]) p[u] = atomicAdd(&g_deg[d[u]], 1);
#pragma unroll
    for (int u = 0; u < U; u++)
        if (ok[u] && p[u] < CAP) g_srcs[(size_t)d[u] * CAP + p[u]] = s[u];
}

// dinv from final degrees + graph offsets from sorted-batch boundaries.
__global__ void meta_kernel(const void* __restrict__ bat) {
    int is64 = g_is64;
    int i = blockIdx.x * blockDim.x + threadIdx.x;
    int stride = gridDim.x * blockDim.x;
    for (int n = i; n < NN; n += stride) {
        g_dinv[n] = rsqrtf((float)(g_deg[n] + 1));
        int b = idx_at(bat, is64, n);
        int bp = (n == 0) ? -1 : idx_at(bat, is64, n - 1);
        for (int g = bp + 1; g <= b; g++) g_goff[g] = n;
        if (n == NN - 1)
            for (int g = b + 1; g <= GG; g++) g_goff[g] = NN;
    }
}

// Tensor-core GEMM: out[row,:] = (X[row,:] @ W) * dinv[row].
// m16n8k8 tf32 mma. 96-row blocks, 192 threads = 6 warps x 16 rows.
// PTX tf32 fragment layout:
//   A: a0=(g,t) a1=(g+8,t) a2=(g,t+4) a3=(g+8,t+4)
//   B: b0=(k=t,n=g) b1=(k=t+4,n=g)
//   C: c0=(g,2t) c1=(g,2t+1) c2=(g+8,2t) c3=(g+8,2t+1)
__global__ __launch_bounds__(192) void gemm_tc(const float* __restrict__ X,
                                               const float* __restrict__ W,
                                               float* __restrict__ out,
                                               int n) {
    __shared__ unsigned Xs[GRROWS][68];   // X tile, pre-converted to tf32
    __shared__ unsigned Wt[64][68];       // W converted to tf32, [k][n]
    const int tid = threadIdx.x;
    const int brow = blockIdx.x * GRROWS;

    for (int t = tid; t < 64 * 16; t += 192) {
        int r = t >> 4, c = (t & 15) << 2;
        float4 w = *(const float4*)(W + r * 64 + c);
        Wt[r][c] = f2tf(w.x); Wt[r][c + 1] = f2tf(w.y);
        Wt[r][c + 2] = f2tf(w.z); Wt[r][c + 3] = f2tf(w.w);
    }
    for (int t = tid; t < GRROWS * 16; t += 192) {
        int r = t >> 4, c = (t & 15) << 2;
        int grow = brow + r;
        float4 v = make_float4(0.f, 0.f, 0.f, 0.f);
        if (grow < n) v = *(const float4*)(X + (size_t)grow * 64 + c);
        Xs[r][c] = f2tf(v.x); Xs[r][c + 1] = f2tf(v.y);
        Xs[r][c + 2] = f2tf(v.z); Xs[r][c + 3] = f2tf(v.w);
    }
    __syncthreads();

    const int wid = tid >> 5, lane = tid & 31;
    const int g = lane >> 2, t4 = lane & 3;
    const int wr = wid * 16;

    float acc[8][4];
#pragma unroll
    for (int nt = 0; nt < 8; nt++)
#pragma unroll
        for (int j = 0; j < 4; j++) acc[nt][j] = 0.f;

#pragma unroll
    for (int kt = 0; kt < 8; kt++) {
        int k0 = kt * 8;
        unsigned a0 = Xs[wr + g][k0 + t4];
        unsigned a1 = Xs[wr + g + 8][k0 + t4];
        unsigned a2 = Xs[wr + g][k0 + t4 + 4];
        unsigned a3 = Xs[wr + g + 8][k0 + t4 + 4];
#pragma unroll
        for (int nt = 0; nt < 8; nt++) {
            unsigned b0 = Wt[k0 + t4][nt * 8 + g];
            unsigned b1 = Wt[k0 + t4 + 4][nt * 8 + g];
            asm("mma.sync.aligned.m16n8k8.row.col.f32.tf32.tf32.f32 "
                "{%0,%1,%2,%3}, {%4,%5,%6,%7}, {%8,%9}, {%0,%1,%2,%3};"
                : "+f"(acc[nt][0]), "+f"(acc[nt][1]),
                  "+f"(acc[nt][2]), "+f"(acc[nt][3])
                : "r"(a0), "r"(a1), "r"(a2), "r"(a3), "r"(b0), "r"(b1));
        }
    }

    int row0 = brow + wr + g;
    int row1 = row0 + 8;
    if (row0 < n) {
        float dv = g_dinv[row0];
#pragma unroll
        for (int nt = 0; nt < 8; nt++)
            *(float2*)(out + (size_t)row0 * 64 + nt * 8 + 2 * t4) =
                make_float2(acc[nt][0] * dv, acc[nt][1] * dv);
    }
    if (row1 < n) {
        float dv = g_dinv[row1];
#pragma unroll
        for (int nt = 0; nt < 8; nt++)
            *(float2*)(out + (size_t)row1 * 64 + nt * 8 + 2 * t4) =
                make_float2(acc[nt][2] * dv, acc[nt][3] * dv);
    }
}

// Pull-style aggregation: one warp per node, 2 edges per step (half-warps),
// inner loop unrolled x2 -> 4 independent gathers in flight per warp. (R12)
template <bool RELU>
__global__ __launch_bounds__(256) void agg_kernel(const float* __restrict__ gb,
                                                  const float* __restrict__ bias,
                                                  float* __restrict__ out) {
    int warp = (blockIdx.x * blockDim.x + threadIdx.x) >> 5;
    if (warp >= NN) return;
    int lane = threadIdx.x & 31;
    int sub = lane >> 4;          // which of 2 edges per step
    int fc = (lane & 15) << 2;    // feature offset (float4)
    int beg = warp * CAP;
    int end = beg + min(g_deg[warp], CAP);

    float4 accA, accB = make_float4(0.f, 0.f, 0.f, 0.f);
    if (sub == 0) {               // self-loop term loaded once by half-warp 0
        accA = *(const float4*)(gb + (size_t)warp * 64 + fc);
    } else {
        accA = make_float4(0.f, 0.f, 0.f, 0.f);
    }

    int e = beg + sub;
    for (; e + 2 < end; e += 4) {
        int s0 = __ldg(&g_srcs[e]);
        int s1 = __ldg(&g_srcs[e + 2]);
        float4 v0 = __ldg((const float4*)(gb + (size_t)s0 * 64 + fc));
        float4 v1 = __ldg((const float4*)(gb + (size_t)s1 * 64 + fc));
        accA.x += v0.x; accA.y += v0.y; accA.z += v0.z; accA.w += v0.w;
        accB.x += v1.x; accB.y += v1.y; accB.z += v1.z; accB.w += v1.w;
    }
    if (e < end) {
        int s0 = __ldg(&g_srcs[e]);
        float4 v0 = __ldg((const float4*)(gb + (size_t)s0 * 64 + fc));
        accA.x += v0.x; accA.y += v0.y; accA.z += v0.z; accA.w += v0.w;
    }
    accA.x += accB.x; accA.y += accB.y; accA.z += accB.z; accA.w += accB.w;

    // combine the two half-warps
    accA.x += __shfl_xor_sync(0xffffffffu, accA.x, 16);
    accA.y += __shfl_xor_sync(0xffffffffu, accA.y, 16);
    accA.z += __shfl_xor_sync(0xffffffffu, accA.z, 16);
    accA.w += __shfl_xor_sync(0xffffffffu, accA.w, 16);

    if (sub == 0) {
        float dv = g_dinv[warp];
        float4 b = __ldg((const float4*)(bias + fc));
        float4 o;
        o.x = fmaf(accA.x, dv, b.x);
        o.y = fmaf(accA.y, dv, b.y);
        o.z = fmaf(accA.z, dv, b.z);
        o.w = fmaf(accA.w, dv, b.w);
        if (RELU) {
            o.x = fmaxf(o.x, 0.f); o.y = fmaxf(o.y, 0.f);
            o.z = fmaxf(o.z, 0.f); o.w = fmaxf(o.w, 0.f);
        }
        *(float4*)(out + (size_t)warp * 64 + fc) = o;
    }
}

// Fused mean pool + classifier + deg-reset (leaves g_deg = 0 for next run).
// One block per graph, 64 threads.
__global__ __launch_bounds__(64) void poolcls_kernel(
        const float* __restrict__ h, float* __restrict__ reps,
        const float* __restrict__ Wc1, const float* __restrict__ bc1,
        const float* __restrict__ Wc2, const float* __restrict__ bc2,
        float* __restrict__ logits) {
    __shared__ float rep[64];
    __shared__ float tbuf[64];
    int g = blockIdx.x, tid = threadIdx.x;
    int beg = g_goff[g], end = g_goff[g + 1];
    float s = 0.f;
    for (int i = beg; i < end; i++) s += __ldg(h + (size_t)i * 64 + tid);
    float c = (float)max(end - beg, 1);
    float r = s / c;
    reps[g * 64 + tid] = r;
    rep[tid] = r;
    __syncthreads();
    float acc = bc1[tid];
#pragma unroll
    for (int k = 0; k < 64; k++) acc = fmaf(rep[k], __ldg(Wc1 + k * 64 + tid), acc);
    tbuf[tid] = fmaxf(acc, 0.f);
    __syncthreads();
    if (tid < CC) {
        float a = bc2[tid];
#pragma unroll
        for (int k = 0; k < 64; k++) a = fmaf(tbuf[k], __ldg(Wc2 + k * CC + tid), a);
        logits[g * CC + tid] = a;
    }
    // reset deg for the next kernel_launch invocation
    int gt = g * 64 + tid;
    int gstride = GG * 64;
    for (int n = gt; n < NN; n += gstride) g_deg[n] = 0;
}

extern "C" void kernel_launch(void* const* d_in, const int* in_sizes, int n_in,
                              void* d_out, int out_size) {
    const float* x   = (const float*)d_in[0];
    const void*  ei  = d_in[1];
    const void*  bat = d_in[2];
    const float* W1  = (const float*)d_in[3];
    const float* b1  = (const float*)d_in[4];
    const float* W2  = (const float*)d_in[5];
    const float* b2  = (const float*)d_in[6];
    const float* Wc1 = (const float*)d_in[7];
    const float* bc1 = (const float*)d_in[8];
    const float* Wc2 = (const float*)d_in[9];
    const float* bc2 = (const float*)d_in[10];

    float* out_h   = (float*)d_out;                       // [NN, 64]
    float* out_rep = out_h + (size_t)NN * HH;             // [128, 64]
    float* out_log = out_rep + (size_t)GG * HH;           // [128, 16]

    void* pv;
    cudaGetSymbolAddress(&pv, g_feat);
    float* p_feat = (float*)pv;
    cudaGetSymbolAddress(&pv, g_h1);
    float* p_h1 = (float*)pv;

    const int gemm_blocks = (NN + GRROWS - 1) / GRROWS;   // 521
    const int agg_blocks = (NN * 32 + 255) / 256;
    const int scat_blocks = (EE + 256 * 4 - 1) / (256 * 4);   // 782

    scatter_kernel<<<scat_blocks, 256>>>(ei);
    meta_kernel<<<256, 256>>>(bat);

    // Layer 1
    gemm_tc<<<gemm_blocks, 192>>>(x, W1, p_feat, NN);
    agg_kernel<true><<<agg_blocks, 256>>>(p_feat, b1, p_h1);

    // Layer 2 (output h, no relu)
    gemm_tc<<<gemm_blocks, 192>>>(p_h1, W2, p_feat, NN);
    agg_kernel<false><<<agg_blocks, 256>>>(p_feat, b2, out_h);

    // Fused pool + classifier (+ deg reset for next run)
    poolcls_kernel<<<GG, 64>>>(out_h, out_rep, Wc1, bc1, Wc2, bc2, out_log);
}